// round 8
// baseline (speedup 1.0000x reference)
#include <cuda_runtime.h>
#include <cuda_bf16.h>
#include <math.h>
#include <stdint.h>

#define TV     128            // vocab rows per CTA
#define KC     32             // K elements per chunk
#define NTHR   256
#define MAXCTA 1024

// ---------------- per-CTA partial scratch ----------------
__device__ float d_gmax[MAXCTA * 64];
__device__ int   d_gidx[MAXCTA * 64];
__device__ float d_lm  [MAXCTA * 64];
__device__ float d_ls  [MAXCTA * 64];
__device__ float d_tmax[MAXCTA * 64];
__device__ int   d_tidx[MAXCTA * 64];
__device__ float d_tsv [MAXCTA * 64];

// hs split planes, chunk-blocked: [chunk][b][k%32]
__device__ __nv_bfloat16 g_hh[64][64][32];
__device__ __nv_bfloat16 g_hm[64][64][32];

// ---------------- helpers ----------------
__device__ __forceinline__ uint32_t smem_u32(const void* p) {
    uint32_t a;
    asm("{ .reg .u64 t; cvta.to.shared.u64 t, %1; cvt.u32.u64 %0, t; }" : "=r"(a) : "l"(p));
    return a;
}
__device__ __forceinline__ uint32_t cvt2bf(float lo, float hi) {   // pack {lo, hi}
    uint32_t r;
    asm("cvt.rn.bf16x2.f32 %0, %1, %2;" : "=r"(r) : "f"(hi), "f"(lo));
    return r;
}
__device__ __forceinline__ void ldsm4(uint32_t* r, uint32_t addr) {
    asm volatile("ldmatrix.sync.aligned.m8n8.x4.shared.b16 {%0,%1,%2,%3}, [%4];"
        : "=r"(r[0]), "=r"(r[1]), "=r"(r[2]), "=r"(r[3]) : "r"(addr));
}
__device__ __forceinline__ void mma16816(float* c, const uint32_t* a,
                                         uint32_t b0, uint32_t b1) {
    asm volatile("mma.sync.aligned.m16n8k16.row.col.f32.bf16.bf16.f32 "
        "{%0,%1,%2,%3}, {%4,%5,%6,%7}, {%8,%9}, {%0,%1,%2,%3};"
        : "+f"(c[0]), "+f"(c[1]), "+f"(c[2]), "+f"(c[3])
        : "r"(a[0]), "r"(a[1]), "r"(a[2]), "r"(a[3]), "r"(b0), "r"(b1));
}

// ---------------- dtype sniffers ----------------
__device__ __forceinline__ int indices_are_int64(const void* lmh, int nrows) {
    const long long* p = (const long long*)lmh;
    for (int i = 0; i < 32; i++) {
        long long v = p[i];
        if (v < 0 || v >= (long long)nrows) return 0;
    }
    return 1;
}
__device__ __forceinline__ long long load_index(const void* lmh, int i, int is64) {
    return is64 ? ((const long long*)lmh)[i] : (long long)((const int*)lmh)[i];
}
__device__ __forceinline__ int mask_is_bytes(const unsigned char* m) {
    const unsigned int* w = (const unsigned int*)m;
    for (int i = 0; i < 16; i++) if (w[i] & ~1u) return 1;
    return 0;
}
__device__ __forceinline__ int load_mask(const unsigned char* m, int b, int isBytes) {
    return isBytes ? (int)m[b] : ((const int*)m)[b];
}

// split 2 floats into (h pair, m pair) bf16x2
__device__ __forceinline__ void split2(float x0, float x1, uint32_t& hp, uint32_t& mp) {
    hp = cvt2bf(x0, x1);
    float h0 = __uint_as_float(hp << 16);
    float h1 = __uint_as_float(hp & 0xFFFF0000u);
    mp = cvt2bf(x0 - h0, x1 - h1);
}

// =====================================================================
// Prep: gather hs rows, split into 2 bf16 planes, chunk-blocked layout.
// =====================================================================
__global__ void __launch_bounds__(NTHR)
prep_kernel(const float* __restrict__ hs, const void* __restrict__ lmh,
            int D, int nrows)
{
    __shared__ int s_is64;
    const int b = blockIdx.x, tid = threadIdx.x;
    if (tid == 0) s_is64 = indices_are_int64(lmh, nrows);
    __syncthreads();
    const long long r = load_index(lmh, b, s_is64);
    const float* src = hs + (size_t)r * D;

    const int k0 = tid * 8;
    if (k0 < D) {
        float4 A = *(const float4*)(src + k0);
        float4 Bv = *(const float4*)(src + k0 + 4);
        uint32_t h01, m01, h23, m23, h45, m45, h67, m67;
        split2(A.x, A.y, h01, m01); split2(A.z, A.w, h23, m23);
        split2(Bv.x, Bv.y, h45, m45); split2(Bv.z, Bv.w, h67, m67);
        const int c = k0 >> 5, ko = k0 & 31;
        *(uint4*)&g_hh[c][b][ko] = make_uint4(h01, h23, h45, h67);
        *(uint4*)&g_hm[c][b][ko] = make_uint4(m01, m23, m45, m67);
    }
}

// =====================================================================
// Main: mma.sync bf16 3-term GEMM, ILP-ordered MMAs, fused epilogue.
// =====================================================================
__global__ void __launch_bounds__(NTHR, 2)
logits_main_kernel(const float* __restrict__ W,
                   const float* __restrict__ temp,
                   const float* __restrict__ gum,
                   int V, int D)
{
    __shared__ __align__(16) uint16_t sWh[128][40];
    __shared__ __align__(16) uint16_t sWm[128][40];
    __shared__ __align__(16) uint16_t sHh[64][40];
    __shared__ __align__(16) uint16_t sHm[64][40];
    __shared__ float sL[8][132];
    __shared__ float sInv[64];

    const int tid = threadIdx.x, lane = tid & 31, wid = tid >> 5;
    const int vbase = blockIdx.x * TV;
    const int nchunk = D / KC;

    if (tid < 64) sInv[tid] = 1.0f / temp[tid];

    // W load mapping: rows v = (tid>>3) + 32*i, cols (tid&7)*4..+3
    const int vr = tid >> 3, kq = tid & 7;
    const float* wbase = W + (size_t)(vbase + vr) * D + kq * 4;
    const __nv_bfloat16* hhbase = &g_hh[0][0][0];
    const __nv_bfloat16* hmbase = &g_hm[0][0][0];

    float4 wf[4];
    uint4 hhq, hmq;
    // prefetch chunk 0
#pragma unroll
    for (int i = 0; i < 4; i++)
        wf[i] = *(const float4*)(wbase + (size_t)(32 * i) * D);
    hhq = *(const uint4*)(hhbase + tid * 8);
    hmq = *(const uint4*)(hmbase + tid * 8);

    float acc[8][4];
#pragma unroll
    for (int n = 0; n < 8; n++)
#pragma unroll
        for (int j = 0; j < 4; j++) acc[n][j] = 0.f;

    // per-lane ldmatrix base offsets
    const uint32_t whB = smem_u32(sWh), wmB = smem_u32(sWm);
    const uint32_t hhB = smem_u32(sHh), hmB = smem_u32(sHm);
    const int q = lane >> 3, r8 = lane & 7;
    const uint32_t aoff = (uint32_t)((16 * wid + ((q & 1) << 3) + r8) * 80
                                     + (((q >> 1) << 3) << 1));
    const uint32_t boff = (uint32_t)(((((q >> 1) << 3) + r8) * 80)
                                     + (((q & 1) << 3) << 1));

    for (int c = 0; c < nchunk; c++) {
        __syncthreads();                      // previous chunk's mma done
        // convert + STS W planes
#pragma unroll
        for (int i = 0; i < 4; i++) {
            uint32_t hp0, mp0, hp1, mp1;
            split2(wf[i].x, wf[i].y, hp0, mp0);
            split2(wf[i].z, wf[i].w, hp1, mp1);
            const int row = vr + 32 * i;
            *(uint2*)&sWh[row][kq * 4] = make_uint2(hp0, hp1);
            *(uint2*)&sWm[row][kq * 4] = make_uint2(mp0, mp1);
        }
        // stage H planes
        {
            const int hb = tid >> 2, hk = (tid & 3) * 8;
            *(uint4*)&sHh[hb][hk] = hhq;
            *(uint4*)&sHm[hb][hk] = hmq;
        }
        __syncthreads();                      // buffers ready

        // prefetch next chunk (overlaps mma)
        if (c + 1 < nchunk) {
#pragma unroll
            for (int i = 0; i < 4; i++)
                wf[i] = *(const float4*)(wbase + (size_t)(32 * i) * D + (c + 1) * KC);
            hhq = *(const uint4*)(hhbase + (size_t)(c + 1) * 2048 + tid * 8);
            hmq = *(const uint4*)(hmbase + (size_t)(c + 1) * 2048 + tid * 8);
        }

        // A fragments (2 planes x 2 ktiles)
        uint32_t ah[2][4], am[2][4];
        ldsm4(ah[0], whB + aoff);
        ldsm4(ah[1], whB + aoff + 32);
        ldsm4(am[0], wmB + aoff);
        ldsm4(am[1], wmB + aoff + 32);

        // B fragments: all 4 np tiles of the hh plane (bb[np][0..3]=ktile0, [4..7]=ktile1)
        uint32_t bb[4][8];
#pragma unroll
        for (int np = 0; np < 4; np++) {
            ldsm4(&bb[np][0], hhB + boff + np * 1280);
            ldsm4(&bb[np][4], hhB + boff + np * 1280 + 32);
        }
        // term 1: ah * bh   (8 independent accumulators per kt -> distance-8 chains)
#pragma unroll
        for (int kt = 0; kt < 2; kt++)
#pragma unroll
            for (int np = 0; np < 4; np++) {
                mma16816(acc[2 * np],     ah[kt], bb[np][4 * kt],     bb[np][4 * kt + 1]);
                mma16816(acc[2 * np + 1], ah[kt], bb[np][4 * kt + 2], bb[np][4 * kt + 3]);
            }
        // term 2: am * bh
#pragma unroll
        for (int kt = 0; kt < 2; kt++)
#pragma unroll
            for (int np = 0; np < 4; np++) {
                mma16816(acc[2 * np],     am[kt], bb[np][4 * kt],     bb[np][4 * kt + 1]);
                mma16816(acc[2 * np + 1], am[kt], bb[np][4 * kt + 2], bb[np][4 * kt + 3]);
            }
        // reload B with hm plane
#pragma unroll
        for (int np = 0; np < 4; np++) {
            ldsm4(&bb[np][0], hmB + boff + np * 1280);
            ldsm4(&bb[np][4], hmB + boff + np * 1280 + 32);
        }
        // term 3: ah * bm
#pragma unroll
        for (int kt = 0; kt < 2; kt++)
#pragma unroll
            for (int np = 0; np < 4; np++) {
                mma16816(acc[2 * np],     ah[kt], bb[np][4 * kt],     bb[np][4 * kt + 1]);
                mma16816(acc[2 * np + 1], ah[kt], bb[np][4 * kt + 2], bb[np][4 * kt + 3]);
            }
    }

    // ---------------- epilogue: 8 b at a time, gumbel in registers ----------------
    const int bl = 2 * (lane & 3);
    const int vl = 16 * wid + (lane >> 2);

    // warp wid reduces b = 8g + wid; lane needs gum[8g+wid][vbase+4*lane..+3]
    float4 g4 = *(const float4*)(gum + (size_t)wid * V + vbase + lane * 4);   // g = 0

    for (int g = 0; g < 8; g++) {
        sL[bl][vl]         = acc[g][0] * sInv[8 * g + bl];
        sL[bl + 1][vl]     = acc[g][1] * sInv[8 * g + bl + 1];
        sL[bl][vl + 8]     = acc[g][2] * sInv[8 * g + bl];
        sL[bl + 1][vl + 8] = acc[g][3] * sInv[8 * g + bl + 1];
        __syncthreads();

        const float4 gcur = g4;
        if (g + 1 < 8)   // prefetch next gumbel row (hides latency behind reduce)
            g4 = *(const float4*)(gum + (size_t)(8 * (g + 1) + wid) * V + vbase + lane * 4);

        {
            float gm = -3.4e38f; int gi = 0x7fffffff;
            float m = -3.4e38f, se = 0.f;
            float tm = -3.4e38f; int ti = 0x7fffffff; float tsl = 0.f;
            const float gv[4] = {gcur.x, gcur.y, gcur.z, gcur.w};
#pragma unroll
            for (int i = 0; i < 4; i++) {
                const int idx = 4 * lane + i;
                const float x = sL[wid][idx];
                const int vg = vbase + idx;
                if (x > gm) { gm = x; gi = vg; }
                if (x > m) { se = se * expf(m - x) + 1.f; m = x; }
                else       { se += expf(x - m); }
                const float tb = x + gv[i];
                if (tb > tm) { tm = tb; ti = vg; tsl = x; }
            }
#pragma unroll
            for (int off = 16; off > 0; off >>= 1) {
                float a2 = __shfl_xor_sync(0xffffffffu, gm, off);
                int  ai2 = __shfl_xor_sync(0xffffffffu, gi, off);
                if (a2 > gm || (a2 == gm && ai2 < gi)) { gm = a2; gi = ai2; }
                float m2 = __shfl_xor_sync(0xffffffffu, m, off);
                float s2 = __shfl_xor_sync(0xffffffffu, se, off);
                const float Mx = fmaxf(m, m2);
                se = se * expf(m - Mx) + s2 * expf(m2 - Mx);
                m = Mx;
                float t2  = __shfl_xor_sync(0xffffffffu, tm, off);
                int  ti2  = __shfl_xor_sync(0xffffffffu, ti, off);
                float ts2 = __shfl_xor_sync(0xffffffffu, tsl, off);
                if (t2 > tm || (t2 == tm && ti2 < ti)) { tm = t2; ti = ti2; tsl = ts2; }
            }
            if (lane == 0) {
                const int o = blockIdx.x * 64 + 8 * g + wid;
                d_gmax[o] = gm; d_gidx[o] = gi;
                d_lm[o]   = m;  d_ls[o]   = se;
                d_tmax[o] = tm; d_tidx[o] = ti; d_tsv[o] = tsl;
            }
        }
        __syncthreads();
    }
}

// =====================================================================
// Reduce: one CTA per batch row, merge nCta partials, emit fp32 pair.
// =====================================================================
__global__ void __launch_bounds__(256)
logits_reduce_kernel(const unsigned char* __restrict__ mask,
                     float* __restrict__ out, int nCta, int B)
{
    const int b = blockIdx.x;
    const int tid = threadIdx.x;

    float gm = -3.4e38f; int gi = 0x7fffffff;
    float m  = -3.4e38f; float se = 0.f;
    float tm = -3.4e38f; int ti = 0x7fffffff; float tsl = 0.f;

    for (int i = tid; i < nCta; i += blockDim.x) {
        const int o = i * 64 + b;
        float a = d_gmax[o]; int ai = d_gidx[o];
        if (a > gm || (a == gm && ai < gi)) { gm = a; gi = ai; }
        float m2 = d_lm[o], s2 = d_ls[o];
        float M = fmaxf(m, m2);
        se = se * expf(m - M) + s2 * expf(m2 - M);
        m = M;
        float t2 = d_tmax[o]; int ti2 = d_tidx[o]; float ts2 = d_tsv[o];
        if (t2 > tm || (t2 == tm && ti2 < ti)) { tm = t2; ti = ti2; tsl = ts2; }
    }
#pragma unroll
    for (int off = 16; off > 0; off >>= 1) {
        float gm2 = __shfl_xor_sync(0xffffffffu, gm, off);
        int   gi2 = __shfl_xor_sync(0xffffffffu, gi, off);
        if (gm2 > gm || (gm2 == gm && gi2 < gi)) { gm = gm2; gi = gi2; }
        float m2  = __shfl_xor_sync(0xffffffffu, m,  off);
        float se2 = __shfl_xor_sync(0xffffffffu, se, off);
        float M = fmaxf(m, m2);
        se = se * expf(m - M) + se2 * expf(m2 - M);
        m = M;
        float tm2 = __shfl_xor_sync(0xffffffffu, tm,  off);
        int   ti2 = __shfl_xor_sync(0xffffffffu, ti,  off);
        float ts2 = __shfl_xor_sync(0xffffffffu, tsl, off);
        if (tm2 > tm || (tm2 == tm && ti2 < ti)) { tm = tm2; ti = ti2; tsl = ts2; }
    }

    __shared__ float sgm[8]; __shared__ int sgi[8];
    __shared__ float sm_[8]; __shared__ float sse[8];
    __shared__ float stm[8]; __shared__ int sti[8]; __shared__ float sts[8];
    const int wid = tid >> 5, lane = tid & 31;
    if (lane == 0) {
        sgm[wid] = gm; sgi[wid] = gi;
        sm_[wid] = m;  sse[wid] = se;
        stm[wid] = tm; sti[wid] = ti; sts[wid] = tsl;
    }
    __syncthreads();

    if (tid == 0) {
        for (int i = 1; i < 8; i++) {
            float a = sgm[i]; int ai = sgi[i];
            if (a > gm || (a == gm && ai < gi)) { gm = a; gi = ai; }
            float m2 = sm_[i], s2 = sse[i];
            float M = fmaxf(m, m2);
            se = se * expf(m - M) + s2 * expf(m2 - M);
            m = M;
            float t2 = stm[i]; int ti2 = sti[i]; float ts2 = sts[i];
            if (t2 > tm || (t2 == tm && ti2 < ti)) { tm = t2; ti = ti2; tsl = ts2; }
        }
        const float Lg = m + logf(se);
        const int isBytes = mask_is_bytes(mask);
        const int mv = load_mask(mask, b, isBytes);
        int id; float sval;
        if (mv != 0) { id = gi; sval = gm;  }
        else         { id = ti; sval = tsl; }
        out[b]     = (float)id;
        out[B + b] = sval - Lg;
    }
}

// =====================================================================
extern "C" void kernel_launch(void* const* d_in, const int* in_sizes, int n_in,
                              void* d_out, int out_size)
{
    const float*         hs   = (const float*)d_in[0];
    const float*         W    = (const float*)d_in[1];
    const float*         temp = (const float*)d_in[2];
    const float*         gum  = (const float*)d_in[3];
    const void*          lmh  = d_in[4];
    const unsigned char* mask = (const unsigned char*)d_in[5];

    const int B = in_sizes[2];            // 64
    const int D = in_sizes[0] / B;        // 2048
    const int V = in_sizes[1] / D;        // 128000
    const int nrowsHS = in_sizes[0] / D;  // 64
    const int nCta = V / TV;              // 1000

    prep_kernel<<<B, NTHR>>>(hs, lmh, D, nrowsHS);
    logits_main_kernel<<<nCta, NTHR>>>(W, temp, gum, V, D);
    logits_reduce_kernel<<<B, 256>>>(mask, (float*)d_out, nCta, B);
}

// round 9
// speedup vs baseline: 2.1446x; 2.1446x over previous
#include <cuda_runtime.h>
#include <cuda_bf16.h>
#include <math.h>
#include <stdint.h>

#define TV     128            // vocab rows per CTA
#define KC     32             // K elements per chunk
#define NTHR   256
#define MAXCTA 1024

// ---------------- per-CTA partial scratch ----------------
__device__ float d_gmax[MAXCTA * 64];
__device__ int   d_gidx[MAXCTA * 64];
__device__ float d_lm  [MAXCTA * 64];
__device__ float d_ls  [MAXCTA * 64];
__device__ float d_tmax[MAXCTA * 64];
__device__ int   d_tidx[MAXCTA * 64];
__device__ float d_tsv [MAXCTA * 64];

// hs split planes, chunk-blocked: [chunk][b][k%32]
__device__ __nv_bfloat16 g_hh[64][64][32];
__device__ __nv_bfloat16 g_hm[64][64][32];

// ---------------- dynamic smem layout (bytes) ----------------
#define OFF_WH(b) ((b) * 10240)                 // 128 x 40 x 2B
#define OFF_WM(b) (20480 + (b) * 10240)
#define OFF_HH(b) (40960 + (b) * 5120)          // 64 x 40 x 2B
#define OFF_HM(b) (51200 + (b) * 5120)
#define OFF_L     61440                          // 8 x 132 x 4B
#define OFF_G     65664                          // 8 x 132 x 4B
#define OFF_INV   69888                          // 64 x 4B
#define SMEM_TOTAL 70144

// ---------------- helpers ----------------
__device__ __forceinline__ uint32_t smem_u32(const void* p) {
    uint32_t a;
    asm("{ .reg .u64 t; cvta.to.shared.u64 t, %1; cvt.u32.u64 %0, t; }" : "=r"(a) : "l"(p));
    return a;
}
__device__ __forceinline__ uint32_t cvt2bf(float lo, float hi) {   // pack {lo, hi}
    uint32_t r;
    asm("cvt.rn.bf16x2.f32 %0, %1, %2;" : "=r"(r) : "f"(hi), "f"(lo));
    return r;
}
__device__ __forceinline__ void ldsm4(uint32_t* r, uint32_t addr) {
    asm volatile("ldmatrix.sync.aligned.m8n8.x4.shared.b16 {%0,%1,%2,%3}, [%4];"
        : "=r"(r[0]), "=r"(r[1]), "=r"(r[2]), "=r"(r[3]) : "r"(addr));
}
__device__ __forceinline__ void mma16816(float* c, const uint32_t* a,
                                         uint32_t b0, uint32_t b1) {
    asm volatile("mma.sync.aligned.m16n8k16.row.col.f32.bf16.bf16.f32 "
        "{%0,%1,%2,%3}, {%4,%5,%6,%7}, {%8,%9}, {%0,%1,%2,%3};"
        : "+f"(c[0]), "+f"(c[1]), "+f"(c[2]), "+f"(c[3])
        : "r"(a[0]), "r"(a[1]), "r"(a[2]), "r"(a[3]), "r"(b0), "r"(b1));
}

// ---------------- dtype sniffers ----------------
__device__ __forceinline__ int indices_are_int64(const void* lmh, int nrows) {
    const long long* p = (const long long*)lmh;
    for (int i = 0; i < 32; i++) {
        long long v = p[i];
        if (v < 0 || v >= (long long)nrows) return 0;
    }
    return 1;
}
__device__ __forceinline__ long long load_index(const void* lmh, int i, int is64) {
    return is64 ? ((const long long*)lmh)[i] : (long long)((const int*)lmh)[i];
}
__device__ __forceinline__ int mask_is_bytes(const unsigned char* m) {
    const unsigned int* w = (const unsigned int*)m;
    for (int i = 0; i < 16; i++) if (w[i] & ~1u) return 1;
    return 0;
}
__device__ __forceinline__ int load_mask(const unsigned char* m, int b, int isBytes) {
    return isBytes ? (int)m[b] : ((const int*)m)[b];
}

// split 2 floats into (h pair, m pair) bf16x2
__device__ __forceinline__ void split2(float x0, float x1, uint32_t& hp, uint32_t& mp) {
    hp = cvt2bf(x0, x1);
    float h0 = __uint_as_float(hp << 16);
    float h1 = __uint_as_float(hp & 0xFFFF0000u);
    mp = cvt2bf(x0 - h0, x1 - h1);
}

// convert register-held chunk into smem buffer `buf`
__device__ __forceinline__ void convert_chunk(char* sm, int buf, int vr, int kq, int tid,
                                              const float4* wf, uint4 hhq, uint4 hmq) {
    uint16_t* wh = (uint16_t*)(sm + OFF_WH(buf));
    uint16_t* wm = (uint16_t*)(sm + OFF_WM(buf));
#pragma unroll
    for (int i = 0; i < 4; i++) {
        uint32_t hp0, mp0, hp1, mp1;
        split2(wf[i].x, wf[i].y, hp0, mp0);
        split2(wf[i].z, wf[i].w, hp1, mp1);
        const int row = vr + 32 * i;
        *(uint2*)&wh[row * 40 + kq * 4] = make_uint2(hp0, hp1);
        *(uint2*)&wm[row * 40 + kq * 4] = make_uint2(mp0, mp1);
    }
    const int hb = tid >> 2, hk = (tid & 3) * 8;
    *(uint4*)((uint16_t*)(sm + OFF_HH(buf)) + hb * 40 + hk) = hhq;
    *(uint4*)((uint16_t*)(sm + OFF_HM(buf)) + hb * 40 + hk) = hmq;
}

// =====================================================================
// Prep: gather hs rows, split into 2 bf16 planes, chunk-blocked layout.
// =====================================================================
__global__ void __launch_bounds__(NTHR)
prep_kernel(const float* __restrict__ hs, const void* __restrict__ lmh,
            int D, int nrows)
{
    __shared__ int s_is64;
    const int b = blockIdx.x, tid = threadIdx.x;
    if (tid == 0) s_is64 = indices_are_int64(lmh, nrows);
    __syncthreads();
    const long long r = load_index(lmh, b, s_is64);
    const float* src = hs + (size_t)r * D;

    const int k0 = tid * 8;
    if (k0 < D) {
        float4 A = *(const float4*)(src + k0);
        float4 Bv = *(const float4*)(src + k0 + 4);
        uint32_t h01, m01, h23, m23, h45, m45, h67, m67;
        split2(A.x, A.y, h01, m01); split2(A.z, A.w, h23, m23);
        split2(Bv.x, Bv.y, h45, m45); split2(Bv.z, Bv.w, h67, m67);
        const int c = k0 >> 5, ko = k0 & 31;
        *(uint4*)&g_hh[c][b][ko] = make_uint4(h01, h23, h45, h67);
        *(uint4*)&g_hm[c][b][ko] = make_uint4(m01, m23, m45, m67);
    }
}

// =====================================================================
// Main: double-buffered mma.sync bf16 3-term GEMM (convert after MMA,
// one barrier per chunk), fused epilogue (R6 form).
// =====================================================================
__global__ void __launch_bounds__(NTHR, 2)
logits_main_kernel(const float* __restrict__ W,
                   const float* __restrict__ temp,
                   const float* __restrict__ gum,
                   int V, int D)
{
    extern __shared__ char sm[];
    const int tid = threadIdx.x, lane = tid & 31, wid = tid >> 5;
    const int vbase = blockIdx.x * TV;
    const int nchunk = D / KC;

    float* sInv = (float*)(sm + OFF_INV);
    float* sL   = (float*)(sm + OFF_L);
    float* sG   = (float*)(sm + OFF_G);

    if (tid < 64) sInv[tid] = 1.0f / temp[tid];

    // W load mapping: rows v = (tid>>3) + 32*i, cols (tid&7)*4..+3
    const int vr = tid >> 3, kq = tid & 7;
    const float* wbase = W + (size_t)(vbase + vr) * D + kq * 4;
    const __nv_bfloat16* hhbase = &g_hh[0][0][0];
    const __nv_bfloat16* hmbase = &g_hm[0][0][0];

    float4 wf[4];
    uint4 hhq, hmq;

    // ---- prologue: chunk 0 -> regs -> buf0; prefetch chunk 1 -> regs ----
#pragma unroll
    for (int i = 0; i < 4; i++)
        wf[i] = *(const float4*)(wbase + (size_t)(32 * i) * D);
    hhq = *(const uint4*)(hhbase + tid * 8);
    hmq = *(const uint4*)(hmbase + tid * 8);
    convert_chunk(sm, 0, vr, kq, tid, wf, hhq, hmq);
#pragma unroll
    for (int i = 0; i < 4; i++)
        wf[i] = *(const float4*)(wbase + (size_t)(32 * i) * D + KC);
    hhq = *(const uint4*)(hhbase + 2048 + tid * 8);
    hmq = *(const uint4*)(hmbase + 2048 + tid * 8);
    __syncthreads();

    float acc[8][4];
#pragma unroll
    for (int n = 0; n < 8; n++)
#pragma unroll
        for (int j = 0; j < 4; j++) acc[n][j] = 0.f;

    // per-lane ldmatrix offsets (within a plane, row stride 80B)
    const int q = lane >> 3, r8 = lane & 7;
    const uint32_t aoff = (uint32_t)((16 * wid + ((q & 1) << 3) + r8) * 80
                                     + (((q >> 1) << 3) << 1));
    const uint32_t boff = (uint32_t)(((((q >> 1) << 3) + r8) * 80)
                                     + (((q & 1) << 3) << 1));

    for (int c = 0; c < nchunk; c++) {
        const int buf = c & 1;
        const uint32_t whB = smem_u32(sm + OFF_WH(buf));
        const uint32_t wmB = smem_u32(sm + OFF_WM(buf));
        const uint32_t hhB = smem_u32(sm + OFF_HH(buf));
        const uint32_t hmB = smem_u32(sm + OFF_HM(buf));

        // A fragments (2 planes x 2 ktiles)
        uint32_t ah[2][4], am[2][4];
        ldsm4(ah[0], whB + aoff);
        ldsm4(ah[1], whB + aoff + 32);
        ldsm4(am[0], wmB + aoff);
        ldsm4(am[1], wmB + aoff + 32);

#pragma unroll
        for (int np = 0; np < 4; np++) {
            uint32_t bh[2][4], bm[2][4];
            ldsm4(bh[0], hhB + boff + np * 1280);
            ldsm4(bh[1], hhB + boff + np * 1280 + 32);
            ldsm4(bm[0], hmB + boff + np * 1280);
            ldsm4(bm[1], hmB + boff + np * 1280 + 32);
#pragma unroll
            for (int kt = 0; kt < 2; kt++) {
                mma16816(acc[2 * np],     ah[kt], bh[kt][0], bh[kt][1]);
                mma16816(acc[2 * np + 1], ah[kt], bh[kt][2], bh[kt][3]);
                mma16816(acc[2 * np],     ah[kt], bm[kt][0], bm[kt][1]);
                mma16816(acc[2 * np + 1], ah[kt], bm[kt][2], bm[kt][3]);
                mma16816(acc[2 * np],     am[kt], bh[kt][0], bh[kt][1]);
                mma16816(acc[2 * np + 1], am[kt], bh[kt][2], bh[kt][3]);
            }
        }

        // convert chunk c+1 (in regs) into other buffer, prefetch chunk c+2
        if (c + 1 < nchunk) {
            convert_chunk(sm, buf ^ 1, vr, kq, tid, wf, hhq, hmq);
            if (c + 2 < nchunk) {
#pragma unroll
                for (int i = 0; i < 4; i++)
                    wf[i] = *(const float4*)(wbase + (size_t)(32 * i) * D + (c + 2) * KC);
                hhq = *(const uint4*)(hhbase + (size_t)(c + 2) * 2048 + tid * 8);
                hmq = *(const uint4*)(hmbase + (size_t)(c + 2) * 2048 + tid * 8);
            }
        }
        __syncthreads();
    }

    // ---------------- epilogue: 8 b at a time (R6 form) ----------------
    const int bl = 2 * (lane & 3);
    const int vl = 16 * wid + (lane >> 2);

    for (int g = 0; g < 8; g++) {
        // scaled logits slice [8 b][128 v]
        sL[bl * 132 + vl]           = acc[g][0] * sInv[8 * g + bl];
        sL[(bl + 1) * 132 + vl]     = acc[g][1] * sInv[8 * g + bl + 1];
        sL[bl * 132 + vl + 8]       = acc[g][2] * sInv[8 * g + bl];
        sL[(bl + 1) * 132 + vl + 8] = acc[g][3] * sInv[8 * g + bl + 1];
        // gumbel slice (coalesced)
        {
            const int gb = tid >> 5, gv = (tid & 31) * 4;
            float4 gq = *(const float4*)(gum + (size_t)(8 * g + gb) * V + vbase + gv);
            *(float4*)&sG[gb * 132 + gv] = gq;
        }
        __syncthreads();

        // warp w reduces b = 8g + w over 128 v
        {
            float gm = -3.4e38f; int gi = 0x7fffffff;
            float m = -3.4e38f, se = 0.f;
            float tm = -3.4e38f; int ti = 0x7fffffff; float tsl = 0.f;
#pragma unroll
            for (int i = 0; i < 4; i++) {
                const int idx = 4 * lane + i;
                const float x = sL[wid * 132 + idx];
                const float gg = sG[wid * 132 + idx];
                const int vg = vbase + idx;
                if (x > gm) { gm = x; gi = vg; }
                if (x > m) { se = se * expf(m - x) + 1.f; m = x; }
                else       { se += expf(x - m); }
                const float tb = x + gg;
                if (tb > tm) { tm = tb; ti = vg; tsl = x; }
            }
#pragma unroll
            for (int off = 16; off > 0; off >>= 1) {
                float a2 = __shfl_xor_sync(0xffffffffu, gm, off);
                int  ai2 = __shfl_xor_sync(0xffffffffu, gi, off);
                if (a2 > gm || (a2 == gm && ai2 < gi)) { gm = a2; gi = ai2; }
                float m2 = __shfl_xor_sync(0xffffffffu, m, off);
                float s2 = __shfl_xor_sync(0xffffffffu, se, off);
                const float Mx = fmaxf(m, m2);
                se = se * expf(m - Mx) + s2 * expf(m2 - Mx);
                m = Mx;
                float t2  = __shfl_xor_sync(0xffffffffu, tm, off);
                int  ti2  = __shfl_xor_sync(0xffffffffu, ti, off);
                float ts2 = __shfl_xor_sync(0xffffffffu, tsl, off);
                if (t2 > tm || (t2 == tm && ti2 < ti)) { tm = t2; ti = ti2; tsl = ts2; }
            }
            if (lane == 0) {
                const int o = blockIdx.x * 64 + 8 * g + wid;
                d_gmax[o] = gm; d_gidx[o] = gi;
                d_lm[o]   = m;  d_ls[o]   = se;
                d_tmax[o] = tm; d_tidx[o] = ti; d_tsv[o] = tsl;
            }
        }
        __syncthreads();
    }
}

// =====================================================================
// Reduce: one CTA per batch row, merge nCta partials, emit fp32 pair.
// =====================================================================
__global__ void __launch_bounds__(256)
logits_reduce_kernel(const unsigned char* __restrict__ mask,
                     float* __restrict__ out, int nCta, int B)
{
    const int b = blockIdx.x;
    const int tid = threadIdx.x;

    float gm = -3.4e38f; int gi = 0x7fffffff;
    float m  = -3.4e38f; float se = 0.f;
    float tm = -3.4e38f; int ti = 0x7fffffff; float tsl = 0.f;

    for (int i = tid; i < nCta; i += blockDim.x) {
        const int o = i * 64 + b;
        float a = d_gmax[o]; int ai = d_gidx[o];
        if (a > gm || (a == gm && ai < gi)) { gm = a; gi = ai; }
        float m2 = d_lm[o], s2 = d_ls[o];
        float M = fmaxf(m, m2);
        se = se * expf(m - M) + s2 * expf(m2 - M);
        m = M;
        float t2 = d_tmax[o]; int ti2 = d_tidx[o]; float ts2 = d_tsv[o];
        if (t2 > tm || (t2 == tm && ti2 < ti)) { tm = t2; ti = ti2; tsl = ts2; }
    }
#pragma unroll
    for (int off = 16; off > 0; off >>= 1) {
        float gm2 = __shfl_xor_sync(0xffffffffu, gm, off);
        int   gi2 = __shfl_xor_sync(0xffffffffu, gi, off);
        if (gm2 > gm || (gm2 == gm && gi2 < gi)) { gm = gm2; gi = gi2; }
        float m2  = __shfl_xor_sync(0xffffffffu, m,  off);
        float se2 = __shfl_xor_sync(0xffffffffu, se, off);
        float M = fmaxf(m, m2);
        se = se * expf(m - M) + se2 * expf(m2 - M);
        m = M;
        float tm2 = __shfl_xor_sync(0xffffffffu, tm,  off);
        int   ti2 = __shfl_xor_sync(0xffffffffu, ti,  off);
        float ts2 = __shfl_xor_sync(0xffffffffu, tsl, off);
        if (tm2 > tm || (tm2 == tm && ti2 < ti)) { tm = tm2; ti = ti2; tsl = ts2; }
    }

    __shared__ float sgm[8]; __shared__ int sgi[8];
    __shared__ float sm_[8]; __shared__ float sse[8];
    __shared__ float stm[8]; __shared__ int sti[8]; __shared__ float sts[8];
    const int wid = tid >> 5, lane = tid & 31;
    if (lane == 0) {
        sgm[wid] = gm; sgi[wid] = gi;
        sm_[wid] = m;  sse[wid] = se;
        stm[wid] = tm; sti[wid] = ti; sts[wid] = tsl;
    }
    __syncthreads();

    if (tid == 0) {
        for (int i = 1; i < 8; i++) {
            float a = sgm[i]; int ai = sgi[i];
            if (a > gm || (a == gm && ai < gi)) { gm = a; gi = ai; }
            float m2 = sm_[i], s2 = sse[i];
            float M = fmaxf(m, m2);
            se = se * expf(m - M) + s2 * expf(m2 - M);
            m = M;
            float t2 = stm[i]; int ti2 = sti[i]; float ts2 = sts[i];
            if (t2 > tm || (t2 == tm && ti2 < ti)) { tm = t2; ti = ti2; tsl = ts2; }
        }
        const float Lg = m + logf(se);
        const int isBytes = mask_is_bytes(mask);
        const int mv = load_mask(mask, b, isBytes);
        int id; float sval;
        if (mv != 0) { id = gi; sval = gm;  }
        else         { id = ti; sval = tsl; }
        out[b]     = (float)id;
        out[B + b] = sval - Lg;
    }
}

// =====================================================================
extern "C" void kernel_launch(void* const* d_in, const int* in_sizes, int n_in,
                              void* d_out, int out_size)
{
    const float*         hs   = (const float*)d_in[0];
    const float*         W    = (const float*)d_in[1];
    const float*         temp = (const float*)d_in[2];
    const float*         gum  = (const float*)d_in[3];
    const void*          lmh  = d_in[4];
    const unsigned char* mask = (const unsigned char*)d_in[5];

    const int B = in_sizes[2];            // 64
    const int D = in_sizes[0] / B;        // 2048
    const int V = in_sizes[1] / D;        // 128000
    const int nrowsHS = in_sizes[0] / D;  // 64
    const int nCta = V / TV;              // 1000

    cudaFuncSetAttribute(logits_main_kernel,
                         cudaFuncAttributeMaxDynamicSharedMemorySize, SMEM_TOTAL);

    prep_kernel<<<B, NTHR>>>(hs, lmh, D, nrowsHS);
    logits_main_kernel<<<nCta, NTHR, SMEM_TOTAL>>>(W, temp, gum, V, D);
    logits_reduce_kernel<<<B, 256>>>(mask, (float*)d_out, nCta, B);
}